// round 4
// baseline (speedup 1.0000x reference)
#include <cuda_runtime.h>
#include <cuda_bf16.h>

#define NT 2000
#define NS 512
#define NH 64

// Output packing (concatenated flattened tuple, float32):
//   Q  : [NT, NS]        at 0
//   C  : [NT, NS]        at 1,024,000
//   S  : [NT, NS, NH]    at 2,048,000
//   H1 : [NT, NS, NH]    at 67,584,000
//   H2 : [NT, NS, NH]    at 133,120,000
//   Qs : [NT, NS, 3]     at 198,656,000
#define OFF_C   1024000
#define OFF_S   2048000
#define OFF_H1  67584000
#define OFF_H2  133120000
#define OFF_QS  198656000

__device__ __forceinline__ float sigmoidf(float x) {
    return 1.0f / (1.0f + expf(-x));
}

__global__ void __launch_bounds__(32, 16)
soil_cq_kernel(const float* __restrict__ P, const float* __restrict__ T,
               const float* __restrict__ E,
               const float* __restrict__ w,  const float* __restrict__ wk1,
               const float* __restrict__ wk2, const float* __restrict__ we1,
               const float* __restrict__ we2, const float* __restrict__ wl,
               const float* __restrict__ wo,  const float* __restrict__ wc,
               float* __restrict__ out)
{
    const int lane = threadIdx.x;           // 0..31
    const int site = blockIdx.x;            // 0..511
    const int j0 = lane * 2;
    const int j1 = j0 + 1;

    // ---- per-thread parameter precompute (2 hidden units per lane) ----
    const float ew0 = expf(w[j0]) + 1.0f,  ew1 = expf(w[j1]) + 1.0f;
    const float sk10 = sigmoidf(wk1[j0]),  sk11 = sigmoidf(wk1[j1]);
    const float sk20 = sigmoidf(wk2[j0]),  sk21 = sigmoidf(wk2[j1]);
    const float se10 = sigmoidf(we1[j0]),  se11 = sigmoidf(we1[j1]);
    const float se20 = sigmoidf(we2[j0]),  se21 = sigmoidf(we2[j1]);
    const float L0   = expf(wl[j0]),       L1   = expf(wl[j1]);

    // softmax(wo) across the warp's 64 units
    float ex0 = expf(wo[j0]), ex1 = expf(wo[j1]);
    float esum = ex0 + ex1;
    #pragma unroll
    for (int o = 16; o; o >>= 1) esum += __shfl_xor_sync(0xffffffffu, esum, o);
    const float a0 = ex0 / esum, a1 = ex1 / esum;

    // a * r where r = 1/sk2/(1+exp(wc))
    const float ar0 = a0 / (sk20 * (1.0f + expf(wc[j0])));
    const float ar1 = a1 / (sk21 * (1.0f + expf(wc[j1])));

    // ---- state in registers ----
    float s0 = 0.f, s1 = 0.f, h10 = 0.f, h11 = 0.f, h20 = 0.f, h21 = 0.f;

    // ---- output pointers ----
    float* Qp  = out + site;
    float* Cp  = out + OFF_C  + site;
    float* Sp  = out + OFF_S  + (size_t)site * NH + j0;
    float* H1p = out + OFF_H1 + (size_t)site * NH + j0;
    float* H2p = out + OFF_H2 + (size_t)site * NH + j0;
    float* QSp = out + OFF_QS + (size_t)site * 3 + lane;   // only lanes 0..2 store

    // ---- forcings: double-buffered 32-step chunks, lane i holds step t0+i ----
    float pA = P[lane * NS + site];
    float tA = T[lane * NS + site];
    float eA = E[lane * NS + site];

    for (int t0 = 0; t0 < NT; t0 += 32) {
        // prefetch next chunk
        float pB = 0.f, tB = 0.f, eB = 0.f;
        const int tn = t0 + 32 + lane;
        if (tn < NT) {
            pB = P[tn * NS + site];
            tB = T[tn * NS + site];
            eB = E[tn * NS + site];
        }
        int rem = NT - t0; if (rem > 32) rem = 32;

        #pragma unroll 4
        for (int i = 0; i < rem; ++i) {
            const float p = __shfl_sync(0xffffffffu, pA, i);
            const float t = __shfl_sync(0xffffffffu, tA, i);
            const float e = __shfl_sync(0xffffffffu, eA, i);

            const float trel = fmaxf(t, 0.0f);
            const float ppos = (t > 0.0f) ? p : 0.0f;
            const float pneg = (t < 0.0f) ? p : 0.0f;

            // ---- unit 0 ----
            const float m0   = fminf(trel * ew0, s0);
            s0 = s0 - m0 + pneg;
            const float x0   = ppos + m0;
            const float u0   = h10 + h20 + x0;
            const float h1a0 = fmaxf(u0 - L0, 0.0f);
            const float h2a0 = fminf(h1a0 + h20 + x0, L0);
            const float q10  = h1a0 * sk10;
            const float q20  = h2a0 * sk20;
            h10 = fmaxf(h1a0 - q10 - e * se10, 0.0f);
            h20 = fmaxf(h2a0 - 2.0f * q20 - e * se20, 0.0f);

            // ---- unit 1 ----
            const float m1   = fminf(trel * ew1, s1);
            s1 = s1 - m1 + pneg;
            const float x1   = ppos + m1;
            const float u1   = h11 + h21 + x1;
            const float h1a1 = fmaxf(u1 - L1, 0.0f);
            const float h2a1 = fminf(h1a1 + h21 + x1, L1);
            const float q11  = h1a1 * sk11;
            const float q21  = h2a1 * sk21;
            h11 = fmaxf(h1a1 - q11 - e * se11, 0.0f);
            h21 = fmaxf(h2a1 - 2.0f * q21 - e * se21, 0.0f);

            // ---- state stores (contiguous 256B per warp per array) ----
            *(float2*)Sp  = make_float2(s0,  s1);
            *(float2*)H1p = make_float2(h10, h11);
            *(float2*)H2p = make_float2(h20, h21);
            Sp  += NS * NH;
            H1p += NS * NH;
            H2p += NS * NH;

            // ---- warp reduction over 64 hidden units ----
            float qa1 = q10 * a0  + q11 * a1;
            float qa2 = q20 * a0  + q21 * a1;
            float qc  = q20 * ar0 + q21 * ar1;
            #pragma unroll
            for (int o = 16; o; o >>= 1) {
                qa1 += __shfl_xor_sync(0xffffffffu, qa1, o);
                qa2 += __shfl_xor_sync(0xffffffffu, qa2, o);
                qc  += __shfl_xor_sync(0xffffffffu, qc,  o);
            }
            const float Qk = qa1 + qa2;
            const float c  = __fdividef(qc * (1.0f / 64.0f) + 1e-5f, Qk + 1e-5f);

            if (lane == 0) *Qp = Qk;
            if (lane == 1) *Cp = c;
            if (lane < 3)  *QSp = (lane == 0) ? qa1 : ((lane == 1) ? qa2 : 0.0f);
            Qp  += NS;
            Cp  += NS;
            QSp += NS * 3;
        }

        pA = pB; tA = tB; eA = eB;
    }
}

extern "C" void kernel_launch(void* const* d_in, const int* in_sizes, int n_in,
                              void* d_out, int out_size)
{
    (void)in_sizes; (void)n_in; (void)out_size;
    soil_cq_kernel<<<NS, 32>>>(
        (const float*)d_in[0], (const float*)d_in[1], (const float*)d_in[2],
        (const float*)d_in[3], (const float*)d_in[4], (const float*)d_in[5],
        (const float*)d_in[6], (const float*)d_in[7], (const float*)d_in[8],
        (const float*)d_in[9], (const float*)d_in[10],
        (float*)d_out);
}

// round 5
// speedup vs baseline: 1.0008x; 1.0008x over previous
#include <cuda_runtime.h>
#include <cuda_bf16.h>

#define NT 2000
#define NS 512
#define NH 64

// Output packing (concatenated flattened tuple, float32):
//   Q  : [NT, NS]        at 0
//   C  : [NT, NS]        at 1,024,000
//   S  : [NT, NS, NH]    at 2,048,000
//   H1 : [NT, NS, NH]    at 67,584,000
//   H2 : [NT, NS, NH]    at 133,120,000
//   Qs : [NT, NS, 3]     at 198,656,000
#define OFF_C   1024000
#define OFF_S   2048000
#define OFF_H1  67584000
#define OFF_H2  133120000
#define OFF_QS  198656000

__device__ __forceinline__ float sigmoidf(float x) {
    return 1.0f / (1.0f + expf(-x));
}

__global__ void __launch_bounds__(32, 16)
soil_cq_kernel(const float* __restrict__ P, const float* __restrict__ T,
               const float* __restrict__ E,
               const float* __restrict__ w,  const float* __restrict__ wk1,
               const float* __restrict__ wk2, const float* __restrict__ we1,
               const float* __restrict__ we2, const float* __restrict__ wl,
               const float* __restrict__ wo,  const float* __restrict__ wc,
               float* __restrict__ out)
{
    const int lane = threadIdx.x;           // 0..31
    const int site = blockIdx.x;            // 0..511
    const int j0 = lane * 2;
    const int j1 = j0 + 1;

    // ---- per-thread parameter precompute (2 hidden units per lane) ----
    const float ew0 = expf(w[j0]) + 1.0f,  ew1 = expf(w[j1]) + 1.0f;
    const float sk10 = sigmoidf(wk1[j0]),  sk11 = sigmoidf(wk1[j1]);
    const float sk20 = sigmoidf(wk2[j0]),  sk21 = sigmoidf(wk2[j1]);
    const float se10 = sigmoidf(we1[j0]),  se11 = sigmoidf(we1[j1]);
    const float se20 = sigmoidf(we2[j0]),  se21 = sigmoidf(we2[j1]);
    const float L0   = expf(wl[j0]),       L1   = expf(wl[j1]);

    // softmax(wo) across the warp's 64 units
    float ex0 = expf(wo[j0]), ex1 = expf(wo[j1]);
    float esum = ex0 + ex1;
    #pragma unroll
    for (int o = 16; o; o >>= 1) esum += __shfl_xor_sync(0xffffffffu, esum, o);
    const float a0 = ex0 / esum, a1 = ex1 / esum;

    // a * r where r = 1/sk2/(1+exp(wc))
    const float ar0 = a0 / (sk20 * (1.0f + expf(wc[j0])));
    const float ar1 = a1 / (sk21 * (1.0f + expf(wc[j1])));

    // ---- state in registers ----
    float s0 = 0.f, s1 = 0.f, h10 = 0.f, h11 = 0.f, h20 = 0.f, h21 = 0.f;

    // ---- output pointers ----
    float* Qp  = out + site;
    float* Cp  = out + OFF_C  + site;
    float* Sp  = out + OFF_S  + (size_t)site * NH + j0;
    float* H1p = out + OFF_H1 + (size_t)site * NH + j0;
    float* H2p = out + OFF_H2 + (size_t)site * NH + j0;
    float* QSp = out + OFF_QS + (size_t)site * 3 + lane;   // only lanes 0..2 store

    // ---- forcings: double-buffered 32-step chunks, lane i holds step t0+i ----
    float pA = P[lane * NS + site];
    float tA = T[lane * NS + site];
    float eA = E[lane * NS + site];

    for (int t0 = 0; t0 < NT; t0 += 32) {
        // prefetch next chunk
        float pB = 0.f, tB = 0.f, eB = 0.f;
        const int tn = t0 + 32 + lane;
        if (tn < NT) {
            pB = P[tn * NS + site];
            tB = T[tn * NS + site];
            eB = E[tn * NS + site];
        }
        int rem = NT - t0; if (rem > 32) rem = 32;

        #pragma unroll 4
        for (int i = 0; i < rem; ++i) {
            const float p = __shfl_sync(0xffffffffu, pA, i);
            const float t = __shfl_sync(0xffffffffu, tA, i);
            const float e = __shfl_sync(0xffffffffu, eA, i);

            const float trel = fmaxf(t, 0.0f);
            const float ppos = (t > 0.0f) ? p : 0.0f;
            const float pneg = (t < 0.0f) ? p : 0.0f;

            // ---- unit 0 ----
            const float m0   = fminf(trel * ew0, s0);
            s0 = s0 - m0 + pneg;
            const float x0   = ppos + m0;
            const float u0   = h10 + h20 + x0;
            const float h1a0 = fmaxf(u0 - L0, 0.0f);
            const float h2a0 = fminf(h1a0 + h20 + x0, L0);
            const float q10  = h1a0 * sk10;
            const float q20  = h2a0 * sk20;
            h10 = fmaxf(h1a0 - q10 - e * se10, 0.0f);
            h20 = fmaxf(h2a0 - 2.0f * q20 - e * se20, 0.0f);

            // ---- unit 1 ----
            const float m1   = fminf(trel * ew1, s1);
            s1 = s1 - m1 + pneg;
            const float x1   = ppos + m1;
            const float u1   = h11 + h21 + x1;
            const float h1a1 = fmaxf(u1 - L1, 0.0f);
            const float h2a1 = fminf(h1a1 + h21 + x1, L1);
            const float q11  = h1a1 * sk11;
            const float q21  = h2a1 * sk21;
            h11 = fmaxf(h1a1 - q11 - e * se11, 0.0f);
            h21 = fmaxf(h2a1 - 2.0f * q21 - e * se21, 0.0f);

            // ---- state stores (contiguous 256B per warp per array) ----
            *(float2*)Sp  = make_float2(s0,  s1);
            *(float2*)H1p = make_float2(h10, h11);
            *(float2*)H2p = make_float2(h20, h21);
            Sp  += NS * NH;
            H1p += NS * NH;
            H2p += NS * NH;

            // ---- warp reduction over 64 hidden units ----
            float qa1 = q10 * a0  + q11 * a1;
            float qa2 = q20 * a0  + q21 * a1;
            float qc  = q20 * ar0 + q21 * ar1;
            #pragma unroll
            for (int o = 16; o; o >>= 1) {
                qa1 += __shfl_xor_sync(0xffffffffu, qa1, o);
                qa2 += __shfl_xor_sync(0xffffffffu, qa2, o);
                qc  += __shfl_xor_sync(0xffffffffu, qc,  o);
            }
            const float Qk = qa1 + qa2;
            const float c  = __fdividef(qc * (1.0f / 64.0f) + 1e-5f, Qk + 1e-5f);

            if (lane == 0) *Qp = Qk;
            if (lane == 1) *Cp = c;
            if (lane < 3)  *QSp = (lane == 0) ? qa1 : ((lane == 1) ? qa2 : 0.0f);
            Qp  += NS;
            Cp  += NS;
            QSp += NS * 3;
        }

        pA = pB; tA = tB; eA = eB;
    }
}

extern "C" void kernel_launch(void* const* d_in, const int* in_sizes, int n_in,
                              void* d_out, int out_size)
{
    (void)in_sizes; (void)n_in; (void)out_size;
    soil_cq_kernel<<<NS, 32>>>(
        (const float*)d_in[0], (const float*)d_in[1], (const float*)d_in[2],
        (const float*)d_in[3], (const float*)d_in[4], (const float*)d_in[5],
        (const float*)d_in[6], (const float*)d_in[7], (const float*)d_in[8],
        (const float*)d_in[9], (const float*)d_in[10],
        (float*)d_out);
}

// round 6
// speedup vs baseline: 1.0020x; 1.0012x over previous
#include <cuda_runtime.h>
#include <cuda_bf16.h>

#define NT 2000
#define NS 512
#define NH 64

// Output packing (concatenated flattened tuple, float32):
//   Q  : [NT, NS]        at 0
//   C  : [NT, NS]        at 1,024,000
//   S  : [NT, NS, NH]    at 2,048,000
//   H1 : [NT, NS, NH]    at 67,584,000
//   H2 : [NT, NS, NH]    at 133,120,000
//   Qs : [NT, NS, 3]     at 198,656,000
#define OFF_C   1024000
#define OFF_S   2048000
#define OFF_H1  67584000
#define OFF_H2  133120000
#define OFF_QS  198656000

__device__ __forceinline__ float sigmoidf(float x) {
    return 1.0f / (1.0f + expf(-x));
}

__global__ void __launch_bounds__(32, 16)
soil_cq_kernel(const float* __restrict__ P, const float* __restrict__ T,
               const float* __restrict__ E,
               const float* __restrict__ w,  const float* __restrict__ wk1,
               const float* __restrict__ wk2, const float* __restrict__ we1,
               const float* __restrict__ we2, const float* __restrict__ wl,
               const float* __restrict__ wo,  const float* __restrict__ wc,
               float* __restrict__ out)
{
    const int lane = threadIdx.x;           // 0..31
    const int site = blockIdx.x;            // 0..511
    const int j0 = lane * 2;
    const int j1 = j0 + 1;

    // ---- per-thread parameter precompute (2 hidden units per lane) ----
    const float ew0 = expf(w[j0]) + 1.0f,  ew1 = expf(w[j1]) + 1.0f;
    const float sk10 = sigmoidf(wk1[j0]),  sk11 = sigmoidf(wk1[j1]);
    const float sk20 = sigmoidf(wk2[j0]),  sk21 = sigmoidf(wk2[j1]);
    const float se10 = sigmoidf(we1[j0]),  se11 = sigmoidf(we1[j1]);
    const float se20 = sigmoidf(we2[j0]),  se21 = sigmoidf(we2[j1]);
    const float L0   = expf(wl[j0]),       L1   = expf(wl[j1]);

    // softmax(wo) across the warp's 64 units
    float ex0 = expf(wo[j0]), ex1 = expf(wo[j1]);
    float esum = ex0 + ex1;
    #pragma unroll
    for (int o = 16; o; o >>= 1) esum += __shfl_xor_sync(0xffffffffu, esum, o);
    const float a0 = ex0 / esum, a1 = ex1 / esum;

    // a * r where r = 1/sk2/(1+exp(wc))
    const float ar0 = a0 / (sk20 * (1.0f + expf(wc[j0])));
    const float ar1 = a1 / (sk21 * (1.0f + expf(wc[j1])));

    // ---- state in registers ----
    float s0 = 0.f, s1 = 0.f, h10 = 0.f, h11 = 0.f, h20 = 0.f, h21 = 0.f;

    // ---- output pointers ----
    float* Qp  = out + site;
    float* Cp  = out + OFF_C  + site;
    float* Sp  = out + OFF_S  + (size_t)site * NH + j0;
    float* H1p = out + OFF_H1 + (size_t)site * NH + j0;
    float* H2p = out + OFF_H2 + (size_t)site * NH + j0;
    float* QSp = out + OFF_QS + (size_t)site * 3 + lane;   // only lanes 0..2 store

    // ---- forcings: double-buffered 32-step chunks, lane i holds step t0+i ----
    float pA = P[lane * NS + site];
    float tA = T[lane * NS + site];
    float eA = E[lane * NS + site];

    for (int t0 = 0; t0 < NT; t0 += 32) {
        // prefetch next chunk
        float pB = 0.f, tB = 0.f, eB = 0.f;
        const int tn = t0 + 32 + lane;
        if (tn < NT) {
            pB = P[tn * NS + site];
            tB = T[tn * NS + site];
            eB = E[tn * NS + site];
        }
        int rem = NT - t0; if (rem > 32) rem = 32;

        #pragma unroll 4
        for (int i = 0; i < rem; ++i) {
            const float p = __shfl_sync(0xffffffffu, pA, i);
            const float t = __shfl_sync(0xffffffffu, tA, i);
            const float e = __shfl_sync(0xffffffffu, eA, i);

            const float trel = fmaxf(t, 0.0f);
            const float ppos = (t > 0.0f) ? p : 0.0f;
            const float pneg = (t < 0.0f) ? p : 0.0f;

            // ---- unit 0 ----
            const float m0   = fminf(trel * ew0, s0);
            s0 = s0 - m0 + pneg;
            const float x0   = ppos + m0;
            const float u0   = h10 + h20 + x0;
            const float h1a0 = fmaxf(u0 - L0, 0.0f);
            const float h2a0 = fminf(h1a0 + h20 + x0, L0);
            const float q10  = h1a0 * sk10;
            const float q20  = h2a0 * sk20;
            h10 = fmaxf(h1a0 - q10 - e * se10, 0.0f);
            h20 = fmaxf(h2a0 - 2.0f * q20 - e * se20, 0.0f);

            // ---- unit 1 ----
            const float m1   = fminf(trel * ew1, s1);
            s1 = s1 - m1 + pneg;
            const float x1   = ppos + m1;
            const float u1   = h11 + h21 + x1;
            const float h1a1 = fmaxf(u1 - L1, 0.0f);
            const float h2a1 = fminf(h1a1 + h21 + x1, L1);
            const float q11  = h1a1 * sk11;
            const float q21  = h2a1 * sk21;
            h11 = fmaxf(h1a1 - q11 - e * se11, 0.0f);
            h21 = fmaxf(h2a1 - 2.0f * q21 - e * se21, 0.0f);

            // ---- state stores (contiguous 256B per warp per array) ----
            *(float2*)Sp  = make_float2(s0,  s1);
            *(float2*)H1p = make_float2(h10, h11);
            *(float2*)H2p = make_float2(h20, h21);
            Sp  += NS * NH;
            H1p += NS * NH;
            H2p += NS * NH;

            // ---- warp reduction over 64 hidden units ----
            float qa1 = q10 * a0  + q11 * a1;
            float qa2 = q20 * a0  + q21 * a1;
            float qc  = q20 * ar0 + q21 * ar1;
            #pragma unroll
            for (int o = 16; o; o >>= 1) {
                qa1 += __shfl_xor_sync(0xffffffffu, qa1, o);
                qa2 += __shfl_xor_sync(0xffffffffu, qa2, o);
                qc  += __shfl_xor_sync(0xffffffffu, qc,  o);
            }
            const float Qk = qa1 + qa2;
            const float c  = __fdividef(qc * (1.0f / 64.0f) + 1e-5f, Qk + 1e-5f);

            if (lane == 0) *Qp = Qk;
            if (lane == 1) *Cp = c;
            if (lane < 3)  *QSp = (lane == 0) ? qa1 : ((lane == 1) ? qa2 : 0.0f);
            Qp  += NS;
            Cp  += NS;
            QSp += NS * 3;
        }

        pA = pB; tA = tB; eA = eB;
    }
}

extern "C" void kernel_launch(void* const* d_in, const int* in_sizes, int n_in,
                              void* d_out, int out_size)
{
    (void)in_sizes; (void)n_in; (void)out_size;
    soil_cq_kernel<<<NS, 32>>>(
        (const float*)d_in[0], (const float*)d_in[1], (const float*)d_in[2],
        (const float*)d_in[3], (const float*)d_in[4], (const float*)d_in[5],
        (const float*)d_in[6], (const float*)d_in[7], (const float*)d_in[8],
        (const float*)d_in[9], (const float*)d_in[10],
        (float*)d_out);
}